// round 2
// baseline (speedup 1.0000x reference)
#include <cuda_runtime.h>
#include <cstdint>

// Problem constants: B=4, S=2048, H=1024, NH=1, DH=1024, DT=32
#define BB 4
#define SS 2048
#define HH 1024
#define MM (BB*SS)          // 8192 total rows

// ---------------- scratch (static device globals; no runtime alloc) ----------------
__device__ float g_Q[(long long)MM*HH];
__device__ float g_K[(long long)MM*HH];
__device__ float g_V[(long long)MM*HH];
__device__ float g_S[(long long)BB*SS*SS];   // scores -> probs in place
__device__ float g_ctx[(long long)MM*HH];
__device__ float g_x[(long long)MM*HH];
__device__ float g_wdd[MM];

// ---------------- generic tiled SGEMM ----------------
// C[m,n] = sum_k A[m,k] * B'[k,n]  (+bias[n]) (+resid[m,n])
// BT=true : B is (N,K) row-major  -> NT gemm (C = A * B^T)
// BT=false: B is (K,N) row-major  -> NN gemm (C = A * B)
// blockIdx.z batches via strides sA,sB,sC. All of M,N divisible by 128, K by 16.
template<bool BT>
__global__ __launch_bounds__(256)
void sgemm(const float* __restrict__ A, const float* __restrict__ Bm,
           const float* __restrict__ bias, const float* __restrict__ resid,
           float* __restrict__ C, int M, int N, int K,
           long long sA, long long sB, long long sC)
{
    constexpr int BM = 128, BN = 128, BK = 16;
    __shared__ float As[BK][BM + 4];
    __shared__ float Bs[BK][BN + 4];

    const int tid = threadIdx.x;
    const int tx = tid & 15;        // 0..15 -> 8 cols each
    const int ty = tid >> 4;        // 0..15 -> 8 rows each
    const int row0 = blockIdx.y * BM;
    const int col0 = blockIdx.x * BN;

    const float* Ap = A  + (long long)blockIdx.z * sA;
    const float* Bp = Bm + (long long)blockIdx.z * sB;
    float*       Cp = C  + (long long)blockIdx.z * sC;

    float acc[8][8];
    #pragma unroll
    for (int i = 0; i < 8; i++)
        #pragma unroll
        for (int j = 0; j < 8; j++) acc[i][j] = 0.f;

    for (int k0 = 0; k0 < K; k0 += BK) {
        // load A tile (128 x 16), store transposed
        #pragma unroll
        for (int i = 0; i < 2; i++) {
            int idx = tid + i * 256;        // 0..511 float4s
            int r = idx >> 2;               // row 0..127
            int c4 = idx & 3;               // float4 col 0..3
            float4 v = *(const float4*)(Ap + (long long)(row0 + r) * K + k0 + c4 * 4);
            As[c4*4+0][r] = v.x; As[c4*4+1][r] = v.y;
            As[c4*4+2][r] = v.z; As[c4*4+3][r] = v.w;
        }
        if constexpr (BT) {
            // B is (N,K): load 128 rows x 16 K, store transposed like A
            #pragma unroll
            for (int i = 0; i < 2; i++) {
                int idx = tid + i * 256;
                int r = idx >> 2;
                int c4 = idx & 3;
                float4 v = *(const float4*)(Bp + (long long)(col0 + r) * K + k0 + c4 * 4);
                Bs[c4*4+0][r] = v.x; Bs[c4*4+1][r] = v.y;
                Bs[c4*4+2][r] = v.z; Bs[c4*4+3][r] = v.w;
            }
        } else {
            // B is (K,N): load 16 rows x 128 cols, direct
            #pragma unroll
            for (int i = 0; i < 2; i++) {
                int idx = tid + i * 256;    // 16 rows x 32 float4
                int r = idx >> 5;           // 0..15
                int c4 = idx & 31;          // 0..31
                float4 v = *(const float4*)(Bp + (long long)(k0 + r) * N + col0 + c4 * 4);
                *(float4*)&Bs[r][c4 * 4] = v;
            }
        }
        __syncthreads();

        #pragma unroll
        for (int kk = 0; kk < BK; kk++) {
            float a[8], b[8];
            *(float4*)&a[0] = *(const float4*)&As[kk][ty * 8];
            *(float4*)&a[4] = *(const float4*)&As[kk][ty * 8 + 4];
            *(float4*)&b[0] = *(const float4*)&Bs[kk][tx * 8];
            *(float4*)&b[4] = *(const float4*)&Bs[kk][tx * 8 + 4];
            #pragma unroll
            for (int i = 0; i < 8; i++)
                #pragma unroll
                for (int j = 0; j < 8; j++)
                    acc[i][j] = fmaf(a[i], b[j], acc[i][j]);
        }
        __syncthreads();
    }

    // epilogue
    #pragma unroll
    for (int i = 0; i < 8; i++) {
        int r = row0 + ty * 8 + i;
        long long base = (long long)r * N;
        #pragma unroll
        for (int j = 0; j < 8; j += 4) {
            int c = col0 + tx * 8 + j;
            float4 v = make_float4(acc[i][j], acc[i][j+1], acc[i][j+2], acc[i][j+3]);
            if (bias) {
                v.x += bias[c]; v.y += bias[c+1]; v.z += bias[c+2]; v.w += bias[c+3];
            }
            if (resid) {
                float4 rr = *(const float4*)(resid + (long long)blockIdx.z * sC + base + c);
                v.x += rr.x; v.y += rr.y; v.z += rr.z; v.w += rr.w;
            }
            *(float4*)(Cp + base + c) = v;
        }
    }
}

// ---------------- per-query distance scalar: wdd[b,q] = Q[b,q,:] . dist_emb[1,:] ----------------
__global__ __launch_bounds__(256)
void wdd_kernel(const float* __restrict__ Q, const float* __restrict__ dist_emb,
                float* __restrict__ wdd)
{
    const int row = blockIdx.x;
    const float* q = Q + (long long)row * HH;
    const float* d = dist_emb + HH;     // row 1
    float s = 0.f;
    for (int i = threadIdx.x; i < HH; i += 256) s = fmaf(q[i], d[i], s);
    #pragma unroll
    for (int o = 16; o; o >>= 1) s += __shfl_xor_sync(0xffffffffu, s, o);
    __shared__ float sh[8];
    if ((threadIdx.x & 31) == 0) sh[threadIdx.x >> 5] = s;
    __syncthreads();
    if (threadIdx.x == 0) {
        float t = 0.f;
        #pragma unroll
        for (int i = 0; i < 8; i++) t += sh[i];
        wdd[row] = t;
    }
}

// ---------------- softmax with distance bias + mask, in place on g_S ----------------
// rel is int32 on the wire (JAX x64 disabled downcasts the requested int64).
__global__ __launch_bounds__(256)
void softmax_kernel(float* __restrict__ S, const int* __restrict__ rel,
                    const float* __restrict__ mask, const float* __restrict__ wdd)
{
    const long long row = blockIdx.x;          // b*S + q, 0..8191
    const int b = (int)(row >> 11);            // /2048
    float* s = S + row * (long long)SS;
    const int* r = rel + row * (long long)SS;
    const float* m = mask + (long long)b * SS; // (B,1,1,S) broadcast over q
    const float w = wdd[row];

    float vals[8];
    float mx = -1e30f;
    #pragma unroll
    for (int i = 0; i < 8; i++) {
        int k = threadIdx.x + i * 256;
        float v = s[k];
        if (r[k] == 1) v += w;
        v = v * 0.03125f + m[k];               // / sqrt(1024)
        vals[i] = v;
        mx = fmaxf(mx, v);
    }
    __shared__ float shm[8], shs[8];
    #pragma unroll
    for (int o = 16; o; o >>= 1) mx = fmaxf(mx, __shfl_xor_sync(0xffffffffu, mx, o));
    if ((threadIdx.x & 31) == 0) shm[threadIdx.x >> 5] = mx;
    __syncthreads();
    mx = shm[0];
    #pragma unroll
    for (int i = 1; i < 8; i++) mx = fmaxf(mx, shm[i]);

    float tot = 0.f;
    #pragma unroll
    for (int i = 0; i < 8; i++) { vals[i] = __expf(vals[i] - mx); tot += vals[i]; }
    #pragma unroll
    for (int o = 16; o; o >>= 1) tot += __shfl_xor_sync(0xffffffffu, tot, o);
    if ((threadIdx.x & 31) == 0) shs[threadIdx.x >> 5] = tot;
    __syncthreads();
    tot = 0.f;
    #pragma unroll
    for (int i = 0; i < 8; i++) tot += shs[i];

    const float inv = 1.f / tot;
    #pragma unroll
    for (int i = 0; i < 8; i++) s[threadIdx.x + i * 256] = vals[i] * inv;
}

// ---------------- LayerNorm ----------------
__global__ __launch_bounds__(256)
void ln_kernel(const float* __restrict__ X, const float* __restrict__ g,
               const float* __restrict__ bb, float* __restrict__ out)
{
    const long long row = blockIdx.x;
    const float* x = X + row * HH;
    float v[4];
    float sum = 0.f, sq = 0.f;
    #pragma unroll
    for (int i = 0; i < 4; i++) {
        v[i] = x[threadIdx.x + i * 256];
        sum += v[i];
        sq = fmaf(v[i], v[i], sq);
    }
    __shared__ float s1[8], s2[8];
    #pragma unroll
    for (int o = 16; o; o >>= 1) {
        sum += __shfl_xor_sync(0xffffffffu, sum, o);
        sq  += __shfl_xor_sync(0xffffffffu, sq, o);
    }
    if ((threadIdx.x & 31) == 0) { s1[threadIdx.x >> 5] = sum; s2[threadIdx.x >> 5] = sq; }
    __syncthreads();
    sum = 0.f; sq = 0.f;
    #pragma unroll
    for (int i = 0; i < 8; i++) { sum += s1[i]; sq += s2[i]; }

    const float mean = sum * (1.f / HH);
    const float var  = sq * (1.f / HH) - mean * mean;
    const float inv  = rsqrtf(var + 1e-12f);
    #pragma unroll
    for (int i = 0; i < 4; i++) {
        int k = threadIdx.x + i * 256;
        out[row * HH + k] = (v[i] - mean) * inv * g[k] + bb[k];
    }
}

// ---------------- launch ----------------
extern "C" void kernel_launch(void* const* d_in, const int* in_sizes, int n_in,
                              void* d_out, int out_size)
{
    const float* hidden = (const float*)d_in[0];
    const float* amask  = (const float*)d_in[1];
    const int*   rel    = (const int*)d_in[2];
    const float* Wq = (const float*)d_in[3];
    const float* bq = (const float*)d_in[4];
    const float* Wk = (const float*)d_in[5];
    const float* bk = (const float*)d_in[6];
    const float* Wv = (const float*)d_in[7];
    const float* bv = (const float*)d_in[8];
    const float* dist = (const float*)d_in[9];
    const float* Wo = (const float*)d_in[10];
    const float* bo = (const float*)d_in[11];
    const float* lng = (const float*)d_in[12];
    const float* lnb = (const float*)d_in[13];
    float* out = (float*)d_out;

    float *Qp, *Kp, *Vp, *Sp, *Cp, *Xp, *Wp;
    cudaGetSymbolAddress((void**)&Qp, g_Q);
    cudaGetSymbolAddress((void**)&Kp, g_K);
    cudaGetSymbolAddress((void**)&Vp, g_V);
    cudaGetSymbolAddress((void**)&Sp, g_S);
    cudaGetSymbolAddress((void**)&Cp, g_ctx);
    cudaGetSymbolAddress((void**)&Xp, g_x);
    cudaGetSymbolAddress((void**)&Wp, g_wdd);

    dim3 blk(256);

    // QKV projections: (8192x1024) = X(8192x1024) * W^T + b
    dim3 gq(HH / 128, MM / 128, 1);
    sgemm<true><<<gq, blk>>>(hidden, Wq, bq, nullptr, Qp, MM, HH, HH, 0, 0, 0);
    sgemm<true><<<gq, blk>>>(hidden, Wk, bk, nullptr, Kp, MM, HH, HH, 0, 0, 0);
    sgemm<true><<<gq, blk>>>(hidden, Wv, bv, nullptr, Vp, MM, HH, HH, 0, 0, 0);

    // per-query distance scalar
    wdd_kernel<<<MM, blk>>>(Qp, dist, Wp);

    // scores: per batch (2048x2048) = Q_b * K_b^T
    dim3 gs(SS / 128, SS / 128, BB);
    sgemm<true><<<gs, blk>>>(Qp, Kp, nullptr, nullptr, Sp, SS, SS, HH,
                             (long long)SS * HH, (long long)SS * HH, (long long)SS * SS);

    // softmax with distance bias + attention mask (in place)
    softmax_kernel<<<MM, blk>>>(Sp, rel, amask, Wp);

    // ctx: per batch (2048x1024) = P_b * V_b
    dim3 gp(HH / 128, SS / 128, BB);
    sgemm<false><<<gp, blk>>>(Sp, Vp, nullptr, nullptr, Cp, SS, HH, SS,
                              (long long)SS * SS, (long long)SS * HH, (long long)SS * HH);

    // out projection + bias + residual
    dim3 go(HH / 128, MM / 128, 1);
    sgemm<true><<<go, blk>>>(Cp, Wo, bo, hidden, Xp, MM, HH, HH, 0, 0, 0);

    // LayerNorm -> d_out
    ln_kernel<<<MM, blk>>>(Xp, lng, lnb, out);
}

// round 4
// speedup vs baseline: 1.8180x; 1.8180x over previous
#include <cuda_runtime.h>
#include <cuda_bf16.h>
#include <cstdint>

#define BB 4
#define SS 2048
#define HH 1024
#define MM (BB*SS)

// ---------------- scratch ----------------
__device__ float g_Q[(long long)MM*HH];
__device__ float g_K[(long long)MM*HH];
__device__ float g_V[(long long)MM*HH];
__device__ float g_Vt[(long long)MM*HH];
__device__ float g_S[(long long)BB*SS*SS];
__device__ float g_ctx[(long long)MM*HH];
__device__ float g_x[(long long)MM*HH];
__device__ float g_wdd[MM];

// ---------------- helpers ----------------
__device__ __forceinline__ uint32_t smem_u32(const void* p){
    uint32_t a;
    asm("{ .reg .u64 t; cvta.to.shared.u64 t, %1; cvt.u32.u64 %0, t; }" : "=r"(a) : "l"(p));
    return a;
}

#define LDSM4(r0,r1,r2,r3,addr) \
    asm volatile("ldmatrix.sync.aligned.m8n8.x4.shared.b16 {%0,%1,%2,%3}, [%4];" \
        : "=r"(r0),"=r"(r1),"=r"(r2),"=r"(r3) : "r"(addr))

#define MMA_BF16(d0,d1,d2,d3, a0,a1,a2,a3, b0,b1) \
    asm volatile("mma.sync.aligned.m16n8k16.row.col.f32.bf16.bf16.f32 " \
        "{%0,%1,%2,%3}, {%4,%5,%6,%7}, {%8,%9}, {%0,%1,%2,%3};" \
        : "+f"(d0),"+f"(d1),"+f"(d2),"+f"(d3) \
        : "r"(a0),"r"(a1),"r"(a2),"r"(a3), "r"(b0),"r"(b1))

__device__ __forceinline__ uint32_t bfbits(__nv_bfloat162 h){
    return *reinterpret_cast<uint32_t*>(&h);
}
// split float4 -> bf16 hi pair-regs + lo pair-regs
__device__ __forceinline__ void split4(float4 v, uint32_t& h01, uint32_t& h23,
                                       uint32_t& l01, uint32_t& l23){
    __nv_bfloat162 h0 = __float22bfloat162_rn(make_float2(v.x, v.y));
    __nv_bfloat162 h1 = __float22bfloat162_rn(make_float2(v.z, v.w));
    float2 f0 = __bfloat1622float2(h0);
    float2 f1 = __bfloat1622float2(h1);
    __nv_bfloat162 l0 = __float22bfloat162_rn(make_float2(v.x - f0.x, v.y - f0.y));
    __nv_bfloat162 l1 = __float22bfloat162_rn(make_float2(v.z - f1.x, v.w - f1.y));
    h01 = bfbits(h0); h23 = bfbits(h1); l01 = bfbits(l0); l23 = bfbits(l1);
}

// swizzled byte offset of 16B chunk (row r, k-chunk c) in a [rows][32] bf16 tile
__device__ __forceinline__ uint32_t toff(int r, int c){
    return (uint32_t)(r * 64 + ((c ^ ((r >> 1) & 3)) << 4));
}

// ---------------- tensor-core split-bf16 GEMM (mma.sync HMMA path) ----------------
// C[m,n] = A[m,:] . B[n,:]  (NT, both K-major) + bias + resid. 3-term bf16 split.
// CTA tile 128x64, BK=32, 8 warps of warp-tile 32x32.
constexpr int A_HI = 0, A_LO = 8192, B_HI = 16384, B_LO = 20480;   // bytes

__global__ __launch_bounds__(256, 2)
void tgemm(const float* __restrict__ A, const float* __restrict__ Bm,
           const float* __restrict__ bias, const float* __restrict__ resid,
           float* __restrict__ C, int N, int K,
           long long sA, long long sB, long long sC)
{
    __shared__ __align__(128) uint8_t sm[24576];
    const uint32_t sb = smem_u32(sm);

    const int tid  = threadIdx.x;
    const int wid  = tid >> 5;
    const int lane = tid & 31;
    const int row0 = blockIdx.y * 128;
    const int col0 = blockIdx.x * 64;
    const float* Ap = A + blockIdx.z * sA;
    const float* Bp = Bm + blockIdx.z * sB;
    float* Cp = C + blockIdx.z * sC;

    const int m0w = (wid & 3) * 32;        // warp m offset in CTA tile
    const int n0w = (wid >> 2) * 32;       // warp n offset

    float acc[2][4][4];
    #pragma unroll
    for (int i = 0; i < 2; i++)
        #pragma unroll
        for (int j = 0; j < 4; j++)
            #pragma unroll
            for (int c = 0; c < 4; c++) acc[i][j][c] = 0.f;

    // load-thread mapping
    const int ar = tid >> 1;               // A row 0..127
    const int akh = (tid & 1) * 16;        // A k offset (covers 2 chunks)
    const int br = tid >> 2;               // B row 0..63
    const int bkq = (tid & 3) * 8;         // B k offset (1 chunk)

    const int NC = K / 32;
    for (int it = 0; it < NC; it++) {
        const int k0 = it * 32;
        // ---- load + split + store smem ----
        {
            const float* src = Ap + (long long)(row0 + ar) * K + k0 + akh;
            float4 v0 = *(const float4*)(src);
            float4 v1 = *(const float4*)(src + 4);
            float4 v2 = *(const float4*)(src + 8);
            float4 v3 = *(const float4*)(src + 12);
            uint4 hi, lo;
            split4(v0, hi.x, hi.y, lo.x, lo.y);
            split4(v1, hi.z, hi.w, lo.z, lo.w);
            uint32_t o = toff(ar, akh >> 3);
            *(uint4*)(sm + A_HI + o) = hi;
            *(uint4*)(sm + A_LO + o) = lo;
            split4(v2, hi.x, hi.y, lo.x, lo.y);
            split4(v3, hi.z, hi.w, lo.z, lo.w);
            o = toff(ar, (akh >> 3) + 1);
            *(uint4*)(sm + A_HI + o) = hi;
            *(uint4*)(sm + A_LO + o) = lo;
        }
        {
            const float* src = Bp + (long long)(col0 + br) * K + k0 + bkq;
            float4 v0 = *(const float4*)(src);
            float4 v1 = *(const float4*)(src + 4);
            uint4 hi, lo;
            split4(v0, hi.x, hi.y, lo.x, lo.y);
            split4(v1, hi.z, hi.w, lo.z, lo.w);
            uint32_t o = toff(br, bkq >> 3);
            *(uint4*)(sm + B_HI + o) = hi;
            *(uint4*)(sm + B_LO + o) = lo;
        }
        __syncthreads();

        // ---- compute ----
        #pragma unroll
        for (int ks = 0; ks < 2; ks++) {
            // A fragments (hi & lo), 2 m-frags
            uint32_t ah[2][4], al[2][4];
            #pragma unroll
            for (int mf = 0; mf < 2; mf++) {
                int r = m0w + mf * 16 + (lane & 15);
                int c = ks * 2 + (lane >> 4);
                uint32_t ad = sb + A_HI + toff(r, c);
                LDSM4(ah[mf][0], ah[mf][1], ah[mf][2], ah[mf][3], ad);
                uint32_t ad2 = sb + A_LO + toff(r, c);
                LDSM4(al[mf][0], al[mf][1], al[mf][2], al[mf][3], ad2);
            }
            // B fragments: 4 n-frags x {b0,b1}
            uint32_t bh[4][2], bl[4][2];
            #pragma unroll
            for (int h = 0; h < 2; h++) {
                int r = n0w + lane;            // 32 rows -> 4 matrices of 8
                int c = ks * 2 + h;
                uint32_t bd = sb + B_HI + toff(r, c);
                LDSM4(bh[0][h], bh[1][h], bh[2][h], bh[3][h], bd);
                uint32_t bd2 = sb + B_LO + toff(r, c);
                LDSM4(bl[0][h], bl[1][h], bl[2][h], bl[3][h], bd2);
            }
            #pragma unroll
            for (int mf = 0; mf < 2; mf++)
                #pragma unroll
                for (int nf = 0; nf < 4; nf++) {
                    MMA_BF16(acc[mf][nf][0], acc[mf][nf][1], acc[mf][nf][2], acc[mf][nf][3],
                             ah[mf][0], ah[mf][1], ah[mf][2], ah[mf][3],
                             bh[nf][0], bh[nf][1]);
                    MMA_BF16(acc[mf][nf][0], acc[mf][nf][1], acc[mf][nf][2], acc[mf][nf][3],
                             ah[mf][0], ah[mf][1], ah[mf][2], ah[mf][3],
                             bl[nf][0], bl[nf][1]);
                    MMA_BF16(acc[mf][nf][0], acc[mf][nf][1], acc[mf][nf][2], acc[mf][nf][3],
                             al[mf][0], al[mf][1], al[mf][2], al[mf][3],
                             bh[nf][0], bh[nf][1]);
                }
        }
        __syncthreads();
    }

    // ---- epilogue: direct stores, fused bias/resid ----
    const int cr = lane >> 2;              // row within 16
    const int cc = (lane & 3) * 2;         // col pair
    #pragma unroll
    for (int mf = 0; mf < 2; mf++) {
        #pragma unroll
        for (int half = 0; half < 2; half++) {
            int r = row0 + m0w + mf * 16 + cr + half * 8;
            long long rb = (long long)r * N;
            #pragma unroll
            for (int nf = 0; nf < 4; nf++) {
                int c = col0 + n0w + nf * 8 + cc;
                float2 v;
                v.x = acc[mf][nf][half * 2 + 0];
                v.y = acc[mf][nf][half * 2 + 1];
                if (bias) {
                    float2 bv = *(const float2*)(bias + c);
                    v.x += bv.x; v.y += bv.y;
                }
                if (resid) {
                    float2 rv = *(const float2*)(resid + blockIdx.z * sC + rb + c);
                    v.x += rv.x; v.y += rv.y;
                }
                *(float2*)(Cp + rb + c) = v;
            }
        }
    }
}

// ---------------- transpose V -> Vt ----------------
__global__ __launch_bounds__(256)
void transpose_kernel(const float* __restrict__ V, float* __restrict__ Vt)
{
    __shared__ float t[32][33];
    const float* src = V + (long long)blockIdx.z * SS * HH;
    float* dst = Vt + (long long)blockIdx.z * SS * HH;
    int n0 = blockIdx.x * 32, k0 = blockIdx.y * 32;
    int tx = threadIdx.x, ty = threadIdx.y;   // 32 x 8
    #pragma unroll
    for (int i = 0; i < 4; i++)
        t[ty + 8 * i][tx] = src[(long long)(k0 + ty + 8 * i) * HH + n0 + tx];
    __syncthreads();
    #pragma unroll
    for (int i = 0; i < 4; i++)
        dst[(long long)(n0 + ty + 8 * i) * SS + k0 + tx] = t[tx][ty + 8 * i];
}

// ---------------- wdd ----------------
__global__ __launch_bounds__(256)
void wdd_kernel(const float* __restrict__ Q, const float* __restrict__ dist_emb,
                float* __restrict__ wdd)
{
    const int row = blockIdx.x;
    const float* q = Q + (long long)row * HH;
    const float* d = dist_emb + HH;
    float s = 0.f;
    for (int i = threadIdx.x; i < HH; i += 256) s = fmaf(q[i], d[i], s);
    #pragma unroll
    for (int o = 16; o; o >>= 1) s += __shfl_xor_sync(0xffffffffu, s, o);
    __shared__ float sh[8];
    if ((threadIdx.x & 31) == 0) sh[threadIdx.x >> 5] = s;
    __syncthreads();
    if (threadIdx.x == 0) {
        float t = 0.f;
        #pragma unroll
        for (int i = 0; i < 8; i++) t += sh[i];
        wdd[row] = t;
    }
}

// ---------------- softmax ----------------
__global__ __launch_bounds__(256)
void softmax_kernel(float* __restrict__ S, const int* __restrict__ rel,
                    const float* __restrict__ mask, const float* __restrict__ wdd)
{
    const long long row = blockIdx.x;
    const int b = (int)(row >> 11);
    float* s = S + row * (long long)SS;
    const int* r = rel + row * (long long)SS;
    const float* m = mask + (long long)b * SS;
    const float w = wdd[row];

    float vals[8];
    float mx = -1e30f;
    #pragma unroll
    for (int i = 0; i < 8; i++) {
        int k = threadIdx.x + i * 256;
        float v = s[k];
        if (r[k] == 1) v += w;
        v = v * 0.03125f + m[k];
        vals[i] = v;
        mx = fmaxf(mx, v);
    }
    __shared__ float shm[8], shs[8];
    #pragma unroll
    for (int o = 16; o; o >>= 1) mx = fmaxf(mx, __shfl_xor_sync(0xffffffffu, mx, o));
    if ((threadIdx.x & 31) == 0) shm[threadIdx.x >> 5] = mx;
    __syncthreads();
    mx = shm[0];
    #pragma unroll
    for (int i = 1; i < 8; i++) mx = fmaxf(mx, shm[i]);

    float tot = 0.f;
    #pragma unroll
    for (int i = 0; i < 8; i++) { vals[i] = __expf(vals[i] - mx); tot += vals[i]; }
    #pragma unroll
    for (int o = 16; o; o >>= 1) tot += __shfl_xor_sync(0xffffffffu, tot, o);
    if ((threadIdx.x & 31) == 0) shs[threadIdx.x >> 5] = tot;
    __syncthreads();
    tot = 0.f;
    #pragma unroll
    for (int i = 0; i < 8; i++) tot += shs[i];

    const float inv = 1.f / tot;
    #pragma unroll
    for (int i = 0; i < 8; i++) s[threadIdx.x + i * 256] = vals[i] * inv;
}

// ---------------- LayerNorm ----------------
__global__ __launch_bounds__(256)
void ln_kernel(const float* __restrict__ X, const float* __restrict__ g,
               const float* __restrict__ bb, float* __restrict__ out)
{
    const long long row = blockIdx.x;
    const float* x = X + row * HH;
    float v[4];
    float sum = 0.f, sq = 0.f;
    #pragma unroll
    for (int i = 0; i < 4; i++) {
        v[i] = x[threadIdx.x + i * 256];
        sum += v[i];
        sq = fmaf(v[i], v[i], sq);
    }
    __shared__ float s1[8], s2[8];
    #pragma unroll
    for (int o = 16; o; o >>= 1) {
        sum += __shfl_xor_sync(0xffffffffu, sum, o);
        sq  += __shfl_xor_sync(0xffffffffu, sq, o);
    }
    if ((threadIdx.x & 31) == 0) { s1[threadIdx.x >> 5] = sum; s2[threadIdx.x >> 5] = sq; }
    __syncthreads();
    sum = 0.f; sq = 0.f;
    #pragma unroll
    for (int i = 0; i < 8; i++) { sum += s1[i]; sq += s2[i]; }

    const float mean = sum * (1.f / HH);
    const float var  = sq * (1.f / HH) - mean * mean;
    const float inv  = rsqrtf(var + 1e-12f);
    #pragma unroll
    for (int i = 0; i < 4; i++) {
        int k = threadIdx.x + i * 256;
        out[row * HH + k] = (v[i] - mean) * inv * g[k] + bb[k];
    }
}

// ---------------- launch ----------------
extern "C" void kernel_launch(void* const* d_in, const int* in_sizes, int n_in,
                              void* d_out, int out_size)
{
    const float* hidden = (const float*)d_in[0];
    const float* amask  = (const float*)d_in[1];
    const int*   rel    = (const int*)d_in[2];
    const float* Wq = (const float*)d_in[3];
    const float* bq = (const float*)d_in[4];
    const float* Wk = (const float*)d_in[5];
    const float* bk = (const float*)d_in[6];
    const float* Wv = (const float*)d_in[7];
    const float* bv = (const float*)d_in[8];
    const float* dist = (const float*)d_in[9];
    const float* Wo = (const float*)d_in[10];
    const float* bo = (const float*)d_in[11];
    const float* lng = (const float*)d_in[12];
    const float* lnb = (const float*)d_in[13];
    float* out = (float*)d_out;

    float *Qp, *Kp, *Vp, *Vtp, *Sp, *Cp, *Xp, *Wp;
    cudaGetSymbolAddress((void**)&Qp, g_Q);
    cudaGetSymbolAddress((void**)&Kp, g_K);
    cudaGetSymbolAddress((void**)&Vp, g_V);
    cudaGetSymbolAddress((void**)&Vtp, g_Vt);
    cudaGetSymbolAddress((void**)&Sp, g_S);
    cudaGetSymbolAddress((void**)&Cp, g_ctx);
    cudaGetSymbolAddress((void**)&Xp, g_x);
    cudaGetSymbolAddress((void**)&Wp, g_wdd);

    dim3 blk(256);

    // QKV projections: (8192x1024) = X * W^T + b
    dim3 gq(HH / 64, MM / 128, 1);
    tgemm<<<gq, blk>>>(hidden, Wq, bq, nullptr, Qp, HH, HH, 0, 0, 0);
    tgemm<<<gq, blk>>>(hidden, Wk, bk, nullptr, Kp, HH, HH, 0, 0, 0);
    tgemm<<<gq, blk>>>(hidden, Wv, bv, nullptr, Vp, HH, HH, 0, 0, 0);

    // per-query distance scalar
    wdd_kernel<<<MM, blk>>>(Qp, dist, Wp);

    // transpose V -> Vt
    transpose_kernel<<<dim3(HH / 32, SS / 32, BB), dim3(32, 8)>>>(Vp, Vtp);

    // scores: per batch QK^T
    dim3 gs(SS / 64, SS / 128, BB);
    tgemm<<<gs, blk>>>(Qp, Kp, nullptr, nullptr, Sp, SS, HH,
                       (long long)SS * HH, (long long)SS * HH, (long long)SS * SS);

    // softmax (in place)
    softmax_kernel<<<MM, blk>>>(Sp, rel, amask, Wp);

    // ctx: per batch P . Vt (NT)
    dim3 gp(HH / 64, SS / 128, BB);
    tgemm<<<gp, blk>>>(Sp, Vtp, nullptr, nullptr, Cp, HH, SS,
                       (long long)SS * SS, (long long)HH * SS, (long long)SS * HH);

    // out projection + bias + residual
    dim3 go(HH / 64, MM / 128, 1);
    tgemm<<<go, blk>>>(Cp, Wo, bo, hidden, Xp, HH, HH, 0, 0, 0);

    // LayerNorm -> out
    ln_kernel<<<MM, blk>>>(Xp, lng, lnb, out);
}

// round 5
// speedup vs baseline: 2.4718x; 1.3596x over previous
#include <cuda_runtime.h>
#include <cuda_bf16.h>
#include <cstdint>

#define BB 4
#define SS 2048
#define HH 1024
#define MM (BB*SS)

typedef __nv_bfloat16 bf16;
typedef __nv_bfloat162 bf162;

// ---------------- scratch ----------------
__device__ bf16  g_Xh[MM*HH], g_Xl[MM*HH];
__device__ bf16  g_Wqh[HH*HH], g_Wql[HH*HH];
__device__ bf16  g_Wkh[HH*HH], g_Wkl[HH*HH];
__device__ bf16  g_Wvh[HH*HH], g_Wvl[HH*HH];
__device__ bf16  g_Woh[HH*HH], g_Wol[HH*HH];
__device__ bf16  g_Qh[MM*HH], g_Ql[MM*HH];
__device__ bf16  g_Kh[MM*HH], g_Kl[MM*HH];
__device__ float g_V[(long long)MM*HH];
__device__ bf16  g_Vth[MM*HH], g_Vtl[MM*HH];
__device__ float g_S[(long long)BB*SS*SS];
__device__ bf16  g_Ph[BB*SS*SS], g_Pl[BB*SS*SS];
__device__ bf16  g_Ch[MM*HH], g_Cl[MM*HH];
__device__ float g_x[(long long)MM*HH];
__device__ float g_wdd[MM];

// ---------------- helpers ----------------
__device__ __forceinline__ uint32_t smem_u32(const void* p){
    uint32_t a;
    asm("{ .reg .u64 t; cvta.to.shared.u64 t, %1; cvt.u32.u64 %0, t; }" : "=r"(a) : "l"(p));
    return a;
}
#define LDSM4(r0,r1,r2,r3,addr) \
    asm volatile("ldmatrix.sync.aligned.m8n8.x4.shared.b16 {%0,%1,%2,%3}, [%4];" \
        : "=r"(r0),"=r"(r1),"=r"(r2),"=r"(r3) : "r"(addr))
#define MMA_BF16(d0,d1,d2,d3, a0,a1,a2,a3, b0,b1) \
    asm volatile("mma.sync.aligned.m16n8k16.row.col.f32.bf16.bf16.f32 " \
        "{%0,%1,%2,%3}, {%4,%5,%6,%7}, {%8,%9}, {%0,%1,%2,%3};" \
        : "+f"(d0),"+f"(d1),"+f"(d2),"+f"(d3) \
        : "r"(a0),"r"(a1),"r"(a2),"r"(a3), "r"(b0),"r"(b1))
#define CP16(dst, src) asm volatile("cp.async.cg.shared.global [%0], [%1], 16;" :: "r"(dst), "l"(src))
#define CPCOMMIT() asm volatile("cp.async.commit_group;" ::: "memory")
#define CPWAIT(n)  asm volatile("cp.async.wait_group %0;" :: "n"(n) : "memory")

__device__ __forceinline__ uint32_t bfbits(bf162 h){ return *reinterpret_cast<uint32_t*>(&h); }

__device__ __forceinline__ void split2(float2 v, uint32_t& h, uint32_t& l){
    bf162 h2 = __float22bfloat162_rn(v);
    float2 hf = __bfloat1622float2(h2);
    bf162 l2 = __float22bfloat162_rn(make_float2(v.x - hf.x, v.y - hf.y));
    h = bfbits(h2); l = bfbits(l2);
}

// swizzled byte offset of 16B chunk (row r, k-chunk c in 0..7) in a [rows][64] bf16 tile
__device__ __forceinline__ uint32_t toff8(int r, int c){
    return (uint32_t)(r * 128 + ((c ^ (r & 7)) << 4));
}

// ---------------- split kernel: fp32 -> bf16 hi/lo ----------------
__global__ __launch_bounds__(256)
void split_kernel(const float* __restrict__ src, bf16* __restrict__ hi,
                  bf16* __restrict__ lo, int n4)
{
    int i = blockIdx.x * 256 + threadIdx.x;
    if (i >= n4) return;
    float4 v = *(const float4*)(src + (long long)i * 4);
    uint2 h, l;
    split2(make_float2(v.x, v.y), h.x, l.x);
    split2(make_float2(v.z, v.w), h.y, l.y);
    *(uint2*)(hi + (long long)i * 4) = h;
    *(uint2*)(lo + (long long)i * 4) = l;
}

// ---------------- tensor-core split-bf16 GEMM ----------------
// C[m,n] = (Ah+Al)[m,:] . (Bh+Bl)[n,:] (NT, K-major, hh+hl+lh terms)
// CTA 128x128, BK=64, 512 threads, cp.async double buffer.
// OUTMODE 0: fp32 out (+bias +resid). OUTMODE 1: bf16 hi/lo out (+bias).
constexpr int STAGE = 65536;
constexpr int OA_HI = 0, OA_LO = 16384, OB_HI = 32768, OB_LO = 49152;
constexpr int SMEM_DYN = 2 * STAGE;

template<int OUTMODE>
__global__ __launch_bounds__(512, 1)
void tgemm(const bf16* __restrict__ Ah, const bf16* __restrict__ Al,
           const bf16* __restrict__ Bh, const bf16* __restrict__ Bl,
           const float* __restrict__ bias, const float* __restrict__ resid,
           float* __restrict__ Cf, bf16* __restrict__ Ch, bf16* __restrict__ Cl,
           int N, int K, long long sA, long long sB, long long sC)
{
    extern __shared__ __align__(128) uint8_t sm[];
    const uint32_t sb = smem_u32(sm);
    const int tid = threadIdx.x;
    const int wid = tid >> 5;
    const int lane = tid & 31;
    const int row0 = blockIdx.y * 128;
    const int col0 = blockIdx.x * 128;
    const bf16* Ahp = Ah + blockIdx.z * sA;
    const bf16* Alp = Al + blockIdx.z * sA;
    const bf16* Bhp = Bh + blockIdx.z * sB;
    const bf16* Blp = Bl + blockIdx.z * sB;

    const int m0w = (wid & 3) * 32;
    const int n0w = (wid >> 2) * 32;

    // loader mapping: chunk id = tid and tid+512; r = id>>3 (0..127), c = id&7
    const int rl = tid >> 3;         // 0..63
    const int cl = tid & 7;

    float acc[2][4][4];
    #pragma unroll
    for (int i = 0; i < 2; i++)
        #pragma unroll
        for (int j = 0; j < 4; j++)
            #pragma unroll
            for (int c = 0; c < 4; c++) acc[i][j][c] = 0.f;

    const int NC = K / 64;

    auto issue = [&](int it, int buf) {
        const int k0 = it * 64;
        const uint32_t st = sb + buf * STAGE;
        const long long aoff = (long long)(row0 + rl) * K + k0 + cl * 8;
        const long long boff = (long long)(col0 + rl) * K + k0 + cl * 8;
        const uint32_t o0 = toff8(rl, cl);
        const uint32_t o1 = toff8(rl + 64, cl);
        CP16(st + OA_HI + o0, Ahp + aoff);
        CP16(st + OA_HI + o1, Ahp + aoff + 64LL * K);
        CP16(st + OA_LO + o0, Alp + aoff);
        CP16(st + OA_LO + o1, Alp + aoff + 64LL * K);
        CP16(st + OB_HI + o0, Bhp + boff);
        CP16(st + OB_HI + o1, Bhp + boff + 64LL * K);
        CP16(st + OB_LO + o0, Blp + boff);
        CP16(st + OB_LO + o1, Blp + boff + 64LL * K);
        CPCOMMIT();
    };

    issue(0, 0);

    for (int it = 0; it < NC; it++) {
        const int buf = it & 1;
        if (it + 1 < NC) { issue(it + 1, buf ^ 1); CPWAIT(1); }
        else             { CPWAIT(0); }
        __syncthreads();

        const uint32_t stAh = sb + buf * STAGE + OA_HI;
        const uint32_t stAl = sb + buf * STAGE + OA_LO;
        const uint32_t stBh = sb + buf * STAGE + OB_HI;
        const uint32_t stBl = sb + buf * STAGE + OB_LO;

        #pragma unroll
        for (int ks = 0; ks < 4; ks++) {
            uint32_t ah[2][4], al[2][4];
            const int ca = ks * 2 + (lane >> 4);
            #pragma unroll
            for (int mf = 0; mf < 2; mf++) {
                const int r = m0w + mf * 16 + (lane & 15);
                LDSM4(ah[mf][0], ah[mf][1], ah[mf][2], ah[mf][3], stAh + toff8(r, ca));
                LDSM4(al[mf][0], al[mf][1], al[mf][2], al[mf][3], stAl + toff8(r, ca));
            }
            uint32_t bh[4][2], bl[4][2];
            const int rB = n0w + lane;
            #pragma unroll
            for (int h = 0; h < 2; h++) {
                const int cb = ks * 2 + h;
                LDSM4(bh[0][h], bh[1][h], bh[2][h], bh[3][h], stBh + toff8(rB, cb));
                LDSM4(bl[0][h], bl[1][h], bl[2][h], bl[3][h], stBl + toff8(rB, cb));
            }
            #pragma unroll
            for (int mf = 0; mf < 2; mf++)
                #pragma unroll
                for (int nf = 0; nf < 4; nf++) {
                    MMA_BF16(acc[mf][nf][0], acc[mf][nf][1], acc[mf][nf][2], acc[mf][nf][3],
                             ah[mf][0], ah[mf][1], ah[mf][2], ah[mf][3],
                             bh[nf][0], bh[nf][1]);
                    MMA_BF16(acc[mf][nf][0], acc[mf][nf][1], acc[mf][nf][2], acc[mf][nf][3],
                             ah[mf][0], ah[mf][1], ah[mf][2], ah[mf][3],
                             bl[nf][0], bl[nf][1]);
                    MMA_BF16(acc[mf][nf][0], acc[mf][nf][1], acc[mf][nf][2], acc[mf][nf][3],
                             al[mf][0], al[mf][1], al[mf][2], al[mf][3],
                             bh[nf][0], bh[nf][1]);
                }
        }
        __syncthreads();
    }

    // ---- epilogue ----
    const int cr = lane >> 2;
    const int cc = (lane & 3) * 2;
    #pragma unroll
    for (int mf = 0; mf < 2; mf++) {
        #pragma unroll
        for (int half = 0; half < 2; half++) {
            const int r = row0 + m0w + mf * 16 + cr + half * 8;
            const long long rb = (long long)r * N;
            #pragma unroll
            for (int nf = 0; nf < 4; nf++) {
                const int c = col0 + n0w + nf * 8 + cc;
                float2 v;
                v.x = acc[mf][nf][half * 2 + 0];
                v.y = acc[mf][nf][half * 2 + 1];
                if (bias) {
                    float2 bv = *(const float2*)(bias + c);
                    v.x += bv.x; v.y += bv.y;
                }
                if (OUTMODE == 0) {
                    if (resid) {
                        float2 rv = *(const float2*)(resid + blockIdx.z * sC + rb + c);
                        v.x += rv.x; v.y += rv.y;
                    }
                    *(float2*)(Cf + blockIdx.z * sC + rb + c) = v;
                } else {
                    uint32_t h, l;
                    split2(v, h, l);
                    *(uint32_t*)(Ch + blockIdx.z * sC + rb + c) = h;
                    *(uint32_t*)(Cl + blockIdx.z * sC + rb + c) = l;
                }
            }
        }
    }
}

// ---------------- transpose V (fp32) -> Vt hi/lo (bf16) ----------------
__global__ __launch_bounds__(256)
void transpose_split(const float* __restrict__ V, bf16* __restrict__ Vth,
                     bf16* __restrict__ Vtl)
{
    __shared__ float t[32][33];
    const float* src = V + (long long)blockIdx.z * SS * HH;
    bf16* dh = Vth + (long long)blockIdx.z * SS * HH;
    bf16* dl = Vtl + (long long)blockIdx.z * SS * HH;
    int n0 = blockIdx.x * 32, k0 = blockIdx.y * 32;
    int tx = threadIdx.x, ty = threadIdx.y;   // 32 x 8
    #pragma unroll
    for (int i = 0; i < 4; i++)
        t[ty + 8 * i][tx] = src[(long long)(k0 + ty + 8 * i) * HH + n0 + tx];
    __syncthreads();
    #pragma unroll
    for (int i = 0; i < 4; i++) {
        float v = t[tx][ty + 8 * i];
        bf16 h = __float2bfloat16(v);
        bf16 l = __float2bfloat16(v - __bfloat162float(h));
        long long o = (long long)(n0 + ty + 8 * i) * SS + k0 + tx;
        dh[o] = h; dl[o] = l;
    }
}

// ---------------- wdd from split Q ----------------
__global__ __launch_bounds__(256)
void wdd_kernel(const bf16* __restrict__ Qh, const bf16* __restrict__ Ql,
                const float* __restrict__ dist_emb, float* __restrict__ wdd)
{
    const int row = blockIdx.x;
    const bf16* qh = Qh + (long long)row * HH;
    const bf16* ql = Ql + (long long)row * HH;
    const float* d = dist_emb + HH;
    float s = 0.f;
    for (int i = threadIdx.x; i < HH; i += 256)
        s = fmaf(__bfloat162float(qh[i]) + __bfloat162float(ql[i]), d[i], s);
    #pragma unroll
    for (int o = 16; o; o >>= 1) s += __shfl_xor_sync(0xffffffffu, s, o);
    __shared__ float sh[8];
    if ((threadIdx.x & 31) == 0) sh[threadIdx.x >> 5] = s;
    __syncthreads();
    if (threadIdx.x == 0) {
        float t = 0.f;
        #pragma unroll
        for (int i = 0; i < 8; i++) t += sh[i];
        wdd[row] = t;
    }
}

// ---------------- softmax -> P hi/lo ----------------
__global__ __launch_bounds__(256)
void softmax_kernel(const float* __restrict__ S, const int* __restrict__ rel,
                    const float* __restrict__ mask, const float* __restrict__ wdd,
                    bf16* __restrict__ Ph, bf16* __restrict__ Pl)
{
    const long long row = blockIdx.x;
    const int b = (int)(row >> 11);
    const float* s = S + row * (long long)SS;
    const int* r = rel + row * (long long)SS;
    const float* m = mask + (long long)b * SS;
    const float w = wdd[row];

    float vals[8];
    float mx = -1e30f;
    #pragma unroll
    for (int i = 0; i < 8; i++) {
        int k = threadIdx.x + i * 256;
        float v = s[k];
        if (r[k] == 1) v += w;
        v = v * 0.03125f + m[k];
        vals[i] = v;
        mx = fmaxf(mx, v);
    }
    __shared__ float shm[8], shs[8];
    #pragma unroll
    for (int o = 16; o; o >>= 1) mx = fmaxf(mx, __shfl_xor_sync(0xffffffffu, mx, o));
    if ((threadIdx.x & 31) == 0) shm[threadIdx.x >> 5] = mx;
    __syncthreads();
    mx = shm[0];
    #pragma unroll
    for (int i = 1; i < 8; i++) mx = fmaxf(mx, shm[i]);

    float tot = 0.f;
    #pragma unroll
    for (int i = 0; i < 8; i++) { vals[i] = __expf(vals[i] - mx); tot += vals[i]; }
    #pragma unroll
    for (int o = 16; o; o >>= 1) tot += __shfl_xor_sync(0xffffffffu, tot, o);
    if ((threadIdx.x & 31) == 0) shs[threadIdx.x >> 5] = tot;
    __syncthreads();
    tot = 0.f;
    #pragma unroll
    for (int i = 0; i < 8; i++) tot += shs[i];

    const float inv = 1.f / tot;
    bf16* ph = Ph + row * (long long)SS;
    bf16* pl = Pl + row * (long long)SS;
    #pragma unroll
    for (int i = 0; i < 8; i++) {
        int k = threadIdx.x + i * 256;
        float p = vals[i] * inv;
        bf16 h = __float2bfloat16(p);
        bf16 l = __float2bfloat16(p - __bfloat162float(h));
        ph[k] = h; pl[k] = l;
    }
}

// ---------------- LayerNorm ----------------
__global__ __launch_bounds__(256)
void ln_kernel(const float* __restrict__ X, const float* __restrict__ g,
               const float* __restrict__ bb, float* __restrict__ out)
{
    const long long row = blockIdx.x;
    const float* x = X + row * HH;
    float v[4];
    float sum = 0.f, sq = 0.f;
    #pragma unroll
    for (int i = 0; i < 4; i++) {
        v[i] = x[threadIdx.x + i * 256];
        sum += v[i];
        sq = fmaf(v[i], v[i], sq);
    }
    __shared__ float s1[8], s2[8];
    #pragma unroll
    for (int o = 16; o; o >>= 1) {
        sum += __shfl_xor_sync(0xffffffffu, sum, o);
        sq  += __shfl_xor_sync(0xffffffffu, sq, o);
    }
    if ((threadIdx.x & 31) == 0) { s1[threadIdx.x >> 5] = sum; s2[threadIdx.x >> 5] = sq; }
    __syncthreads();
    sum = 0.f; sq = 0.f;
    #pragma unroll
    for (int i = 0; i < 8; i++) { sum += s1[i]; sq += s2[i]; }

    const float mean = sum * (1.f / HH);
    const float var  = sq * (1.f / HH) - mean * mean;
    const float inv  = rsqrtf(var + 1e-12f);
    #pragma unroll
    for (int i = 0; i < 4; i++) {
        int k = threadIdx.x + i * 256;
        out[row * HH + k] = (v[i] - mean) * inv * g[k] + bb[k];
    }
}

// ---------------- launch ----------------
extern "C" void kernel_launch(void* const* d_in, const int* in_sizes, int n_in,
                              void* d_out, int out_size)
{
    const float* hidden = (const float*)d_in[0];
    const float* amask  = (const float*)d_in[1];
    const int*   rel    = (const int*)d_in[2];
    const float* Wq = (const float*)d_in[3];
    const float* bq = (const float*)d_in[4];
    const float* Wk = (const float*)d_in[5];
    const float* bk = (const float*)d_in[6];
    const float* Wv = (const float*)d_in[7];
    const float* bv = (const float*)d_in[8];
    const float* dist = (const float*)d_in[9];
    const float* Wo = (const float*)d_in[10];
    const float* bo = (const float*)d_in[11];
    const float* lng = (const float*)d_in[12];
    const float* lnb = (const float*)d_in[13];
    float* out = (float*)d_out;

    bf16 *Xh,*Xl,*Wqh,*Wql,*Wkh,*Wkl,*Wvh,*Wvl,*Woh,*Wol;
    bf16 *Qh,*Ql,*Kh,*Kl,*Vth,*Vtl,*Ph,*Pl,*Ch,*Cl;
    float *Vp,*Sp,*Xp,*Wp;
    cudaGetSymbolAddress((void**)&Xh, g_Xh);   cudaGetSymbolAddress((void**)&Xl, g_Xl);
    cudaGetSymbolAddress((void**)&Wqh, g_Wqh); cudaGetSymbolAddress((void**)&Wql, g_Wql);
    cudaGetSymbolAddress((void**)&Wkh, g_Wkh); cudaGetSymbolAddress((void**)&Wkl, g_Wkl);
    cudaGetSymbolAddress((void**)&Wvh, g_Wvh); cudaGetSymbolAddress((void**)&Wvl, g_Wvl);
    cudaGetSymbolAddress((void**)&Woh, g_Woh); cudaGetSymbolAddress((void**)&Wol, g_Wol);
    cudaGetSymbolAddress((void**)&Qh, g_Qh);   cudaGetSymbolAddress((void**)&Ql, g_Ql);
    cudaGetSymbolAddress((void**)&Kh, g_Kh);   cudaGetSymbolAddress((void**)&Kl, g_Kl);
    cudaGetSymbolAddress((void**)&Vth, g_Vth); cudaGetSymbolAddress((void**)&Vtl, g_Vtl);
    cudaGetSymbolAddress((void**)&Ph, g_Ph);   cudaGetSymbolAddress((void**)&Pl, g_Pl);
    cudaGetSymbolAddress((void**)&Ch, g_Ch);   cudaGetSymbolAddress((void**)&Cl, g_Cl);
    cudaGetSymbolAddress((void**)&Vp, g_V);
    cudaGetSymbolAddress((void**)&Sp, g_S);
    cudaGetSymbolAddress((void**)&Xp, g_x);
    cudaGetSymbolAddress((void**)&Wp, g_wdd);

    cudaFuncSetAttribute(tgemm<0>, cudaFuncAttributeMaxDynamicSharedMemorySize, SMEM_DYN);
    cudaFuncSetAttribute(tgemm<1>, cudaFuncAttributeMaxDynamicSharedMemorySize, SMEM_DYN);

    dim3 blk(256);

    // pre-split inputs
    split_kernel<<<MM * HH / 4 / 256, blk>>>(hidden, Xh, Xl, MM * HH / 4);
    split_kernel<<<HH * HH / 4 / 256, blk>>>(Wq, Wqh, Wql, HH * HH / 4);
    split_kernel<<<HH * HH / 4 / 256, blk>>>(Wk, Wkh, Wkl, HH * HH / 4);
    split_kernel<<<HH * HH / 4 / 256, blk>>>(Wv, Wvh, Wvl, HH * HH / 4);
    split_kernel<<<HH * HH / 4 / 256, blk>>>(Wo, Woh, Wol, HH * HH / 4);

    dim3 tb(512);
    // QKV projections
    dim3 gq(HH / 128, MM / 128, 1);
    tgemm<1><<<gq, tb, SMEM_DYN>>>(Xh, Xl, Wqh, Wql, bq, nullptr,
                                   nullptr, Qh, Ql, HH, HH, 0, 0, 0);
    tgemm<1><<<gq, tb, SMEM_DYN>>>(Xh, Xl, Wkh, Wkl, bk, nullptr,
                                   nullptr, Kh, Kl, HH, HH, 0, 0, 0);
    tgemm<0><<<gq, tb, SMEM_DYN>>>(Xh, Xl, Wvh, Wvl, bv, nullptr,
                                   Vp, nullptr, nullptr, HH, HH, 0, 0, 0);

    // per-query distance scalar
    wdd_kernel<<<MM, blk>>>(Qh, Ql, dist, Wp);

    // transpose V -> Vt hi/lo
    transpose_split<<<dim3(HH / 32, SS / 32, BB), dim3(32, 8)>>>(Vp, Vth, Vtl);

    // scores: per batch QK^T -> fp32 S
    dim3 gs(SS / 128, SS / 128, BB);
    tgemm<0><<<gs, tb, SMEM_DYN>>>(Qh, Ql, Kh, Kl, nullptr, nullptr,
                                   Sp, nullptr, nullptr, SS, HH,
                                   (long long)SS * HH, (long long)SS * HH, (long long)SS * SS);

    // softmax -> P hi/lo
    softmax_kernel<<<MM, blk>>>(Sp, rel, amask, Wp, Ph, Pl);

    // ctx: per batch P . Vt^T -> ctx hi/lo
    dim3 gp(HH / 128, SS / 128, BB);
    tgemm<1><<<gp, tb, SMEM_DYN>>>(Ph, Pl, Vth, Vtl, nullptr, nullptr,
                                   nullptr, Ch, Cl, HH, SS,
                                   (long long)SS * SS, (long long)HH * SS, (long long)SS * HH);

    // out projection + bias + residual -> fp32 x
    dim3 go(HH / 128, MM / 128, 1);
    tgemm<0><<<go, tb, SMEM_DYN>>>(Ch, Cl, Woh, Wol, bo, hidden,
                                   Xp, nullptr, nullptr, HH, HH, 0, 0, 0);

    // LayerNorm -> out
    ln_kernel<<<MM, blk>>>(Xp, lng, lnb, out);
}